// round 12
// baseline (speedup 1.0000x reference)
#include <cuda_runtime.h>

// ---------------------------------------------------------------------------
// DLinear_436: per-pixel 48->48 linear map with (hc,wc) position-class weights.
// Trend (window-25 moving avg over T=12, affine in t) folded entirely into the
// weight table by prep.  Prep: separable fold -> 12-slot interleaved table
//   gWi12[hc][o][q][wc][4]   (192B record covers ALL 12 wc classes)
// Intermediates now stored [hc][o][tc][j] so prepA's stores are COALESCED
// (was the hidden 5.2us: scattered 4B STGs -> ~10 wavefronts each).
// Main: 128 blocks x 256 threads, 4 px/thread, ONE wave, ALL threads active.
//   Weight table staged via cp.async.bulk (mbarrier), x LDGs hoisted in front
//   of the wait so both DRAM latencies overlap.
// ---------------------------------------------------------------------------

#define T_IN 12
#define HW   4096
#define NO   48
#define TC   48
#define NCLS 144

#define TAB_FLOATS (48 * 12 * 12 * 4)          // 27648
#define TAB_BYTES  (TAB_FLOATS * 4)            // 110592
#define BIAS_BYTES (576 * 4)                   // 2304
#define SMEM_FLOATS (TAB_FLOATS + 576)         // 28224
#define SMEM_BYTES  (SMEM_FLOATS * 4 + 16)     // + mbarrier

// Final tables
__device__ float gWi12[12][48][12][12][4];     // [hc][o][q][wc][c]
__device__ float gBi12[12][12][12][4];         // [hc][to][wc][co]
// Intermediate separable-fold tables (TRANSPOSED: j fastest -> coalesced STG)
__device__ float gAs[12][NO][TC][8];           // i-folded w_s      [hc][o][tc][j]
__device__ float gAd[12][NO][TC][8];           // i-folded (w_t-w_s)

typedef unsigned long long u64;
#define FMA2(d,a,b,c) asm("fma.rn.f32x2 %0, %1, %2, %3;" : "=l"(d) : "l"(a), "l"(b), "l"(c))
#define UNPACK2(lo,hi,v) asm("mov.b64 {%0, %1}, %2;" : "=f"(lo), "=f"(hi) : "l"(v))

__device__ __forceinline__ unsigned smem_u32(const void* p) {
    unsigned a;
    asm("{ .reg .u64 t; cvta.to.shared.u64 t, %1; cvt.u32.u64 %0, t; }"
        : "=r"(a) : "l"(p));
    return a;
}

__device__ __forceinline__ int class_ilist(int hc, int idx[2]) {
    if (hc < 4)  { idx[0] = hc;                  return 1; }
    if (hc < 8)  { idx[0] = hc - 4; idx[1] = hc; return 2; }
    idx[0] = hc - 4;                             return 1;
}

// ---------------------------------------------------------------------------
// prepA: fold the i axis for all 12 hc classes at once.  18432 threads.
// Thread n = tc_row*8 + j; stores are j-fastest -> 1 wavefront per STG.
// ---------------------------------------------------------------------------
__global__ void dlinear_prepA(const float* __restrict__ w_s,
                              const float* __restrict__ w_t) {
    int n = blockIdx.x * blockDim.x + threadIdx.x;
    if (n >= NO * T_IN * 4 * 8) return;
    int j  = n & 7;
    int tc_row = n >> 3;            // (o*12+t)*4+c
    int t  = (n >> 5) % 12;
    int o  = (n >> 5) / 12;
    int c  = (n >> 3) & 3;
    int tc = t * 4 + c;

    int base = tc_row * 64 + j;
    float v[8], d[8];
    #pragma unroll
    for (int i = 0; i < 8; i++) {
        float a = w_s[base + 8 * i];
        float b = w_t[base + 8 * i];
        v[i] = a;
        d[i] = b - a;
    }
    #pragma unroll
    for (int m = 0; m < 4; m++) {
        gAs[m][o][tc][j]     = v[m];
        gAs[m + 4][o][tc][j] = v[m] + v[m + 4];
        gAs[m + 8][o][tc][j] = v[m + 4];
        gAd[m][o][tc][j]     = d[m];
        gAd[m + 4][o][tc][j] = d[m] + d[m + 4];
        gAd[m + 8][o][tc][j] = d[m + 4];
    }
}

// ---------------------------------------------------------------------------
// prepB: fold j axis per class, inline t-reduction of gAd, absorb trend
// -> gWi12.  Tail threads fold the bias.  338688 threads.
// ---------------------------------------------------------------------------
__global__ void dlinear_prepB(const float* __restrict__ b_s,
                              const float* __restrict__ b_t) {
    int n = blockIdx.x * blockDim.x + threadIdx.x;
    if (n < NCLS * NO * TC) {
        int tc = n % TC;
        int o  = (n / TC) % NO;
        int cls = n / (NO * TC);
        int hc = cls / 12, wc = cls % 12;
        int t = tc >> 2, c = tc & 3;

        int jl[2];
        int nj = class_ilist(wc, jl);

        float s = 0.f, d0 = 0.f, d1 = 0.f;
        for (int e = 0; e < nj; e++) {
            int j = jl[e];
            s += gAs[hc][o][tc][j];
            #pragma unroll
            for (int tt = 0; tt < T_IN; tt++) {
                float d = gAd[hc][o][tt * 4 + c][j];
                d0 += d;
                d1 += (float)tt * d;
            }
        }
        float wv = s + (1.f / 25.f) * d0;
        if (t == 0)  wv += (1.f / 25.f) * (12.f * d0 - d1);
        if (t == 11) wv += (1.f / 25.f) * (d0 + d1);
        gWi12[hc][o][t][wc][c] = wv;
        return;
    }
    int m = n - NCLS * NO * TC;
    if (m < NCLS * NO) {
        int o = m % NO, cls = m / NO;
        int hc = cls / 12, wc = cls % 12;
        int il[2], jl[2];
        int ni = class_ilist(hc, il), nj = class_ilist(wc, jl);
        float s = 0.f;
        for (int a = 0; a < ni; a++)
            for (int e = 0; e < nj; e++) {
                int off = o * 64 + il[a] * 8 + jl[e];
                s += b_s[off] + b_t[off];
            }
        gBi12[hc][o >> 2][wc][o & 3] = s;
    }
}

// ---------------------------------------------------------------------------
// Main.  128 blocks x 256 threads, 4 px/thread, one wave, all threads active.
//   bid = h*2 + half : h in [0,64), half selects b range [half*16, +16).
//   thread: w = tid&63 (lanes contiguous), rr = tid>>6;
//           pixels at b = half*16 + rr + {0,4,8,12}, fixed (h, w).
// Weight table + bias arrive by cp.async.bulk; x LDGs overlap the copy.
// ---------------------------------------------------------------------------
__global__ __launch_bounds__(256, 1)
void dlinear_main_kernel(const float* __restrict__ x, float* __restrict__ out) {
    extern __shared__ float sm[];
    const int tid = threadIdx.x;
    const int bid = blockIdx.x;

    const int h  = bid >> 1;
    const int b0 = (bid & 1) * 16;
    const int hc = (h < 4) ? h : ((h < 60) ? 4 + (h & 3) : 8 + (h & 3));

    const unsigned mbar = smem_u32(sm + SMEM_FLOATS);

    if (tid == 0) {
        asm volatile("mbarrier.init.shared.b64 [%0], 1;" :: "r"(mbar) : "memory");
    }
    __syncthreads();
    if (tid == 0) {
        asm volatile("mbarrier.arrive.expect_tx.shared.b64 _, [%0], %1;"
                     :: "r"(mbar), "r"((unsigned)(TAB_BYTES + BIAS_BYTES)) : "memory");
        asm volatile("cp.async.bulk.shared::cta.global.mbarrier::complete_tx::bytes "
                     "[%0], [%1], %2, [%3];"
                     :: "r"(smem_u32(sm)), "l"(&gWi12[hc][0][0][0][0]),
                        "r"((unsigned)TAB_BYTES), "r"(mbar) : "memory");
        asm volatile("cp.async.bulk.shared::cta.global.mbarrier::complete_tx::bytes "
                     "[%0], [%1], %2, [%3];"
                     :: "r"(smem_u32(sm + TAB_FLOATS)), "l"(&gBi12[hc][0][0][0]),
                        "r"((unsigned)BIAS_BYTES), "r"(mbar) : "memory");
    }

    const int w  = tid & 63;
    const int rr = tid >> 6;
    const int wc = (w < 4) ? w : ((w < 60) ? 4 + (w & 3) : 8 + (w & 3));

    int g[4];
    #pragma unroll
    for (int it = 0; it < 4; it++) {
        int b = b0 + rr + it * 4;
        g[it] = b * T_IN * HW + h * 64 + w;    // in float4 (16B) units
    }

    // ---- x LDGs issued while the bulk copy streams in
    u64 x2[4][24];
    const ulonglong2* xg = (const ulonglong2*)x;
    #pragma unroll
    for (int t = 0; t < T_IN; t++) {
        #pragma unroll
        for (int p = 0; p < 4; p++) {
            ulonglong2 v = xg[g[p] + t * HW];
            x2[p][2 * t] = v.x;  x2[p][2 * t + 1] = v.y;
        }
    }

    // ---- wait for the weight table (acquire orders subsequent smem reads)
    asm volatile(
        "{\n\t"
        ".reg .pred p;\n\t"
        "WAIT_%=:\n\t"
        "mbarrier.try_wait.parity.acquire.cta.shared::cta.b64 p, [%0], 0, 0x989680;\n\t"
        "@!p bra WAIT_%=;\n\t"
        "}" :: "r"(mbar) : "memory");

    // ---- 48 outputs x 4 pixels; lane-slot weight reads within 192B records
    const ulonglong2* wt = (const ulonglong2*)sm;
    const float4* bt = (const float4*)(sm + TAB_FLOATS);
    float4* og = (float4*)out;

    #pragma unroll 1
    for (int to = 0; to < 12; to++) {
        float4 bias = bt[to * 12 + wc];
        const float* bp = (const float*)&bias;
        float res[4][4];
        #pragma unroll
        for (int co = 0; co < 4; co++) {
            const int o = to * 4 + co;
            const ulonglong2* wr = wt + (o * 12) * 12 + wc;
            u64 a0 = 0, a1 = 0, a2 = 0, a3 = 0;
            #pragma unroll
            for (int q = 0; q < 12; q++) {
                ulonglong2 wv = wr[q * 12];
                FMA2(a0, x2[0][2 * q],     wv.x, a0);
                FMA2(a1, x2[1][2 * q],     wv.x, a1);
                FMA2(a2, x2[2][2 * q],     wv.x, a2);
                FMA2(a3, x2[3][2 * q],     wv.x, a3);
                FMA2(a0, x2[0][2 * q + 1], wv.y, a0);
                FMA2(a1, x2[1][2 * q + 1], wv.y, a1);
                FMA2(a2, x2[2][2 * q + 1], wv.y, a2);
                FMA2(a3, x2[3][2 * q + 1], wv.y, a3);
            }
            float lo, hi;
            UNPACK2(lo, hi, a0); res[0][co] = bp[co] + lo + hi;
            UNPACK2(lo, hi, a1); res[1][co] = bp[co] + lo + hi;
            UNPACK2(lo, hi, a2); res[2][co] = bp[co] + lo + hi;
            UNPACK2(lo, hi, a3); res[3][co] = bp[co] + lo + hi;
        }
        #pragma unroll
        for (int p = 0; p < 4; p++)
            og[g[p] + to * HW] = make_float4(res[p][0], res[p][1], res[p][2], res[p][3]);
    }
}

// ---------------------------------------------------------------------------
extern "C" void kernel_launch(void* const* d_in, const int* in_sizes, int n_in,
                              void* d_out, int out_size) {
    const float* x   = (const float*)d_in[0];
    const float* w_s = (const float*)d_in[1];
    const float* b_s = (const float*)d_in[2];
    const float* w_t = (const float*)d_in[3];
    const float* b_t = (const float*)d_in[4];
    float* out = (float*)d_out;

    cudaFuncSetAttribute(dlinear_main_kernel,
                         cudaFuncAttributeMaxDynamicSharedMemorySize, SMEM_BYTES);

    dlinear_prepA<<<72, 256>>>(w_s, w_t);                   // 18432 threads
    dlinear_prepB<<<1323, 256>>>(b_s, b_t);                 // 331776 + 6912
    dlinear_main_kernel<<<128, 256, SMEM_BYTES>>>(x, out);
}

// round 13
// speedup vs baseline: 1.1091x; 1.1091x over previous
#include <cuda_runtime.h>

// ---------------------------------------------------------------------------
// DLinear_436: per-pixel 48->48 linear map with (hc,wc) position-class weights.
// Trend (window-25 moving avg over T=12, affine in t) folded entirely into the
// weight table:  W'[o,t,c] = S + D0/25 + [t==0](12D0-D1)/25 + [t==11](D0+D1)/25
// Prep: ONE fused kernel, block = (o, hc-half).  Loads the 24KB w_s/w_t slice
// for its o coalescedly, does all separable folds in smem (e: t-reduce of d;
// uj: j-fold of ws; ej: j-fold of e), writes gWi12/gBi12 directly.  No gmem
// intermediates (R12's two-stage pipeline spent ~7us on launch+latency).
// Main: 128 blocks x 256 threads, 4 px/thread, one wave, all threads active.
//   Weight table staged via cp.async.bulk (mbarrier), x LDGs hoisted in front
//   of the wait so both DRAM latencies overlap.
// ---------------------------------------------------------------------------

#define T_IN 12
#define HW   4096
#define NO   48
#define TC   48

#define TAB_FLOATS (48 * 12 * 12 * 4)          // 27648
#define TAB_BYTES  (TAB_FLOATS * 4)            // 110592
#define BIAS_BYTES (576 * 4)                   // 2304
#define SMEM_FLOATS (TAB_FLOATS + 576)         // 28224
#define SMEM_BYTES  (SMEM_FLOATS * 4 + 16)     // + mbarrier

// Final tables
__device__ float gWi12[12][48][12][12][4];     // [hc][o][q][wc][c]
__device__ float gBi12[12][12][12][4];         // [hc][to][wc][co]

typedef unsigned long long u64;
#define FMA2(d,a,b,c) asm("fma.rn.f32x2 %0, %1, %2, %3;" : "=l"(d) : "l"(a), "l"(b), "l"(c))
#define UNPACK2(lo,hi,v) asm("mov.b64 {%0, %1}, %2;" : "=f"(lo), "=f"(hi) : "l"(v))

__device__ __forceinline__ unsigned smem_u32(const void* p) {
    unsigned a;
    asm("{ .reg .u64 t; cvta.to.shared.u64 t, %1; cvt.u32.u64 %0, t; }"
        : "=r"(a) : "l"(p));
    return a;
}

__device__ __forceinline__ int class_ilist(int hc, int idx[2]) {
    if (hc < 4)  { idx[0] = hc;                  return 1; }
    if (hc < 8)  { idx[0] = hc - 4; idx[1] = hc; return 2; }
    idx[0] = hc - 4;                             return 1;
}

// ---------------------------------------------------------------------------
// Fused prep.  96 blocks x 256 threads.  bid = o*2 + half; the block emits
// gWi12 for hc in [half*6, half*6+6) at its o, plus the matching bias rows.
// ---------------------------------------------------------------------------
__global__ __launch_bounds__(256)
void dlinear_prep(const float* __restrict__ w_s, const float* __restrict__ w_t,
                  const float* __restrict__ b_s, const float* __restrict__ b_t) {
    __shared__ float ws[3072];      // w_s[o]            [tc][i*8+j]
    __shared__ float ds[3072];      // (w_t - w_s)[o]
    __shared__ float e0[256];       // sum_t ds          [c][i*8+j]
    __shared__ float e1[256];       // sum_t t*ds
    __shared__ float uj[4608];      // j-fold of ws      [tc][i][wc]
    __shared__ float ej0[384];      // j-fold of e0      [c][i][wc]
    __shared__ float ej1[384];
    __shared__ float bsum[64];      // (b_s + b_t)[o]    [i*8+j]

    const int tid  = threadIdx.x;
    const int o    = blockIdx.x >> 1;
    const int half = blockIdx.x & 1;

    // ---- load the o-slice (24KB) coalesced; d computed on the fly
    {
        const float4* s4 = (const float4*)(w_s + o * 3072);
        const float4* t4 = (const float4*)(w_t + o * 3072);
        #pragma unroll
        for (int k = 0; k < 3; k++) {
            float4 a = s4[tid + k * 256];
            float4 b = t4[tid + k * 256];
            ((float4*)ws)[tid + k * 256] = a;
            ((float4*)ds)[tid + k * 256] =
                make_float4(b.x - a.x, b.y - a.y, b.z - a.z, b.w - a.w);
        }
        if (tid < 64) bsum[tid] = b_s[o * 64 + tid] + b_t[o * 64 + tid];
    }
    __syncthreads();

    // ---- phase 1: e (t-reduction of d) and uj (j-fold of ws)
    {
        int c = tid >> 6, z = tid & 63;
        float s0 = 0.f, s1 = 0.f;
        #pragma unroll
        for (int t = 0; t < T_IN; t++) {
            float d = ds[(t * 4 + c) * 64 + z];
            s0 += d;
            s1 += (float)t * d;
        }
        e0[tid] = s0;
        e1[tid] = s1;
    }
    #pragma unroll
    for (int k = 0; k < 18; k++) {
        int n = tid + k * 256;                 // 4608 = 18*256
        int tc = n / 96, rem = n - tc * 96;
        int i = rem / 12, wc = rem - i * 12;
        int jl[2];
        int nj = class_ilist(wc, jl);
        float s = ws[tc * 64 + i * 8 + jl[0]];
        if (nj == 2) s += ws[tc * 64 + i * 8 + jl[1]];
        uj[n] = s;
    }
    __syncthreads();

    // ---- phase 2: ej (j-fold of e)
    #pragma unroll
    for (int k = 0; k < 2; k++) {
        int n = tid + k * 256;
        if (n < 384) {
            int c = n / 96, rem = n - c * 96;
            int i = rem / 12, wc = rem - i * 12;
            int jl[2];
            int nj = class_ilist(wc, jl);
            float s0 = e0[c * 64 + i * 8 + jl[0]];
            float s1 = e1[c * 64 + i * 8 + jl[0]];
            if (nj == 2) {
                s0 += e0[c * 64 + i * 8 + jl[1]];
                s1 += e1[c * 64 + i * 8 + jl[1]];
            }
            ej0[n] = s0;
            ej1[n] = s1;
        }
    }
    __syncthreads();

    // ---- phase 3: outputs for 6 hc values (i-fold + trend absorption)
    #pragma unroll
    for (int k = 0; k < 14; k++) {
        int n = tid + k * 256;                 // 3456 = 6*576
        if (n >= 3456) break;
        int hcL = n / 576, r = n - hcL * 576;
        int hc = half * 6 + hcL;
        int t = r / 48;
        int wc = (r >> 2) % 12;
        int c = r & 3;
        int tc = t * 4 + c;

        int il[2];
        int ni = class_ilist(hc, il);
        float S  = uj [tc * 96 + il[0] * 12 + wc];
        float D0 = ej0[c  * 96 + il[0] * 12 + wc];
        float D1 = ej1[c  * 96 + il[0] * 12 + wc];
        if (ni == 2) {
            S  += uj [tc * 96 + il[1] * 12 + wc];
            D0 += ej0[c  * 96 + il[1] * 12 + wc];
            D1 += ej1[c  * 96 + il[1] * 12 + wc];
        }
        float wv = S + (1.f / 25.f) * D0;
        if (t == 0)  wv += (1.f / 25.f) * (12.f * D0 - D1);
        if (t == 11) wv += (1.f / 25.f) * (D0 + D1);
        ((float*)gWi12)[(hc * 48 + o) * 576 + r] = wv;
    }

    // ---- bias rows for this (o, hc-set)
    if (tid < 72) {
        int hcL = tid / 12, wc = tid - hcL * 12;
        int hc = half * 6 + hcL;
        int il[2], jl[2];
        int ni = class_ilist(hc, il), nj = class_ilist(wc, jl);
        float s = 0.f;
        for (int a = 0; a < ni; a++)
            for (int e = 0; e < nj; e++)
                s += bsum[il[a] * 8 + jl[e]];
        gBi12[hc][o >> 2][wc][o & 3] = s;
    }
}

// ---------------------------------------------------------------------------
// Main.  128 blocks x 256 threads, 4 px/thread, one wave, all threads active.
//   bid = h*2 + half : h in [0,64), half selects b range [half*16, +16).
//   thread: w = tid&63 (lanes contiguous), rr = tid>>6;
//           pixels at b = half*16 + rr + {0,4,8,12}, fixed (h, w).
// Weight table + bias arrive by cp.async.bulk; x LDGs overlap the copy.
// ---------------------------------------------------------------------------
__global__ __launch_bounds__(256, 1)
void dlinear_main_kernel(const float* __restrict__ x, float* __restrict__ out) {
    extern __shared__ float sm[];
    const int tid = threadIdx.x;
    const int bid = blockIdx.x;

    const int h  = bid >> 1;
    const int b0 = (bid & 1) * 16;
    const int hc = (h < 4) ? h : ((h < 60) ? 4 + (h & 3) : 8 + (h & 3));

    const unsigned mbar = smem_u32(sm + SMEM_FLOATS);

    if (tid == 0) {
        asm volatile("mbarrier.init.shared.b64 [%0], 1;" :: "r"(mbar) : "memory");
    }
    __syncthreads();
    if (tid == 0) {
        asm volatile("mbarrier.arrive.expect_tx.shared.b64 _, [%0], %1;"
                     :: "r"(mbar), "r"((unsigned)(TAB_BYTES + BIAS_BYTES)) : "memory");
        asm volatile("cp.async.bulk.shared::cta.global.mbarrier::complete_tx::bytes "
                     "[%0], [%1], %2, [%3];"
                     :: "r"(smem_u32(sm)), "l"(&gWi12[hc][0][0][0][0]),
                        "r"((unsigned)TAB_BYTES), "r"(mbar) : "memory");
        asm volatile("cp.async.bulk.shared::cta.global.mbarrier::complete_tx::bytes "
                     "[%0], [%1], %2, [%3];"
                     :: "r"(smem_u32(sm + TAB_FLOATS)), "l"(&gBi12[hc][0][0][0]),
                        "r"((unsigned)BIAS_BYTES), "r"(mbar) : "memory");
    }

    const int w  = tid & 63;
    const int rr = tid >> 6;
    const int wc = (w < 4) ? w : ((w < 60) ? 4 + (w & 3) : 8 + (w & 3));

    int g[4];
    #pragma unroll
    for (int it = 0; it < 4; it++) {
        int b = b0 + rr + it * 4;
        g[it] = b * T_IN * HW + h * 64 + w;    // in float4 (16B) units
    }

    // ---- x LDGs issued while the bulk copy streams in
    u64 x2[4][24];
    const ulonglong2* xg = (const ulonglong2*)x;
    #pragma unroll
    for (int t = 0; t < T_IN; t++) {
        #pragma unroll
        for (int p = 0; p < 4; p++) {
            ulonglong2 v = xg[g[p] + t * HW];
            x2[p][2 * t] = v.x;  x2[p][2 * t + 1] = v.y;
        }
    }

    // ---- wait for the weight table (acquire orders subsequent smem reads)
    asm volatile(
        "{\n\t"
        ".reg .pred p;\n\t"
        "WAIT_%=:\n\t"
        "mbarrier.try_wait.parity.acquire.cta.shared::cta.b64 p, [%0], 0, 0x989680;\n\t"
        "@!p bra WAIT_%=;\n\t"
        "}" :: "r"(mbar) : "memory");

    // ---- 48 outputs x 4 pixels; lane-slot weight reads within 192B records
    const ulonglong2* wt = (const ulonglong2*)sm;
    const float4* bt = (const float4*)(sm + TAB_FLOATS);
    float4* og = (float4*)out;

    #pragma unroll 1
    for (int to = 0; to < 12; to++) {
        float4 bias = bt[to * 12 + wc];
        const float* bp = (const float*)&bias;
        float res[4][4];
        #pragma unroll
        for (int co = 0; co < 4; co++) {
            const int o = to * 4 + co;
            const ulonglong2* wr = wt + (o * 12) * 12 + wc;
            u64 a0 = 0, a1 = 0, a2 = 0, a3 = 0;
            #pragma unroll
            for (int q = 0; q < 12; q++) {
                ulonglong2 wv = wr[q * 12];
                FMA2(a0, x2[0][2 * q],     wv.x, a0);
                FMA2(a1, x2[1][2 * q],     wv.x, a1);
                FMA2(a2, x2[2][2 * q],     wv.x, a2);
                FMA2(a3, x2[3][2 * q],     wv.x, a3);
                FMA2(a0, x2[0][2 * q + 1], wv.y, a0);
                FMA2(a1, x2[1][2 * q + 1], wv.y, a1);
                FMA2(a2, x2[2][2 * q + 1], wv.y, a2);
                FMA2(a3, x2[3][2 * q + 1], wv.y, a3);
            }
            float lo, hi;
            UNPACK2(lo, hi, a0); res[0][co] = bp[co] + lo + hi;
            UNPACK2(lo, hi, a1); res[1][co] = bp[co] + lo + hi;
            UNPACK2(lo, hi, a2); res[2][co] = bp[co] + lo + hi;
            UNPACK2(lo, hi, a3); res[3][co] = bp[co] + lo + hi;
        }
        #pragma unroll
        for (int p = 0; p < 4; p++)
            og[g[p] + to * HW] = make_float4(res[p][0], res[p][1], res[p][2], res[p][3]);
    }
}

// ---------------------------------------------------------------------------
extern "C" void kernel_launch(void* const* d_in, const int* in_sizes, int n_in,
                              void* d_out, int out_size) {
    const float* x   = (const float*)d_in[0];
    const float* w_s = (const float*)d_in[1];
    const float* b_s = (const float*)d_in[2];
    const float* w_t = (const float*)d_in[3];
    const float* b_t = (const float*)d_in[4];
    float* out = (float*)d_out;

    cudaFuncSetAttribute(dlinear_main_kernel,
                         cudaFuncAttributeMaxDynamicSharedMemorySize, SMEM_BYTES);

    dlinear_prep<<<96, 256>>>(w_s, w_t, b_s, b_t);
    dlinear_main_kernel<<<128, 256, SMEM_BYTES>>>(x, out);
}